// round 11
// baseline (speedup 1.0000x reference)
#include <cuda_runtime.h>
#include <cuda_bf16.h>
#include <math.h>
#include <stdint.h>

#define Bk   4
#define Lk   4096
#define Dk   512
#define DFFk 2048
#define NFk  2049          // rfft bins = L/2+1
#define KTOP 8
#define PI_D 3.14159265358979323846
#define RT   (2*Bk*NFk)    // 16392 spectrum rows (re block ; im block)

// ---------------- scratch (static device globals; no allocation) ----------------
__device__ float  g_V    [Bk*Lk*Dk];
__device__ float  g_Ut   [(size_t)Dk*RT];   // transposed spectrum [d][r]
__device__ float  g_U    [(size_t)RT*Dk];   // [r][d] fp32
__device__ float  g_VU   [(size_t)RT*Dk];   // U @ G
__device__ float2 g_S    [Bk*NFk];
__device__ float  g_corr [Bk*Lk];
__device__ int    g_delay[Bk*KTOP];
__device__ float  g_p    [Bk*KTOP];
__device__ float  g_h    [Bk*Lk*Dk];
__device__ float  g_S1   [Bk*Lk*Dk];
__device__ float  g_h2   [Bk*Lk*Dk];
__device__ float2 g_tw   [Lk/2];
__device__ float  g_G    [Dk*Dk];

// bf16 hi/lo activations (A operands)
__device__ __nv_bfloat16 g_x_h  [Bk*Lk*Dk],    g_x_l  [Bk*Lk*Dk];
__device__ __nv_bfloat16 g_U_h  [(size_t)RT*Dk], g_U_l[(size_t)RT*Dk];
__device__ __nv_bfloat16 g_at_h [Bk*Lk*Dk],    g_at_l [Bk*Lk*Dk];
__device__ __nv_bfloat16 g_S1_h [Bk*Lk*Dk],    g_S1_l [Bk*Lk*Dk];
__device__ __nv_bfloat16 g_hid_h[(size_t)Bk*Lk*DFFk], g_hid_l[(size_t)Bk*Lk*DFFk];

// bf16 split weights ([N,K] layout for mma B operand = W^T)
__device__ __nv_bfloat16 g_Wvt_h[Dk*Dk],  g_Wvt_l[Dk*Dk];
__device__ __nv_bfloat16 g_Wot_h[Dk*Dk],  g_Wot_l[Dk*Dk];
__device__ __nv_bfloat16 g_W1t_h[DFFk*Dk],g_W1t_l[DFFk*Dk];
__device__ __nv_bfloat16 g_W2t_h[Dk*DFFk],g_W2t_l[Dk*DFFk];
__device__ __nv_bfloat16 g_Wq_h [Dk*Dk],  g_Wq_l [Dk*Dk];
__device__ __nv_bfloat16 g_Wk_h [Dk*Dk],  g_Wk_l [Dk*Dk];
__device__ __nv_bfloat16 g_Gt_h [Dk*Dk],  g_Gt_l [Dk*Dk];

// ---------------- helpers ----------------
__device__ __forceinline__ void split2(float v0, float v1, uint32_t& hi, uint32_t& lo) {
    __nv_bfloat162 h = __floats2bfloat162_rn(v0, v1);
    float2 f = __bfloat1622float2(h);
    __nv_bfloat162 l = __floats2bfloat162_rn(v0 - f.x, v1 - f.y);
    hi = *(uint32_t*)&h; lo = *(uint32_t*)&l;
}
__device__ __forceinline__ void cpa16(uint32_t dst, const void* src) {
    asm volatile("cp.async.cg.shared.global [%0], [%1], 16;" :: "r"(dst), "l"(src));
}
__device__ __forceinline__ void cpa_commit() { asm volatile("cp.async.commit_group;"); }
__device__ __forceinline__ void mma16816(float* c, const uint32_t* a,
                                         uint32_t b0, uint32_t b1) {
    asm volatile(
        "mma.sync.aligned.m16n8k16.row.col.f32.bf16.bf16.f32 "
        "{%0,%1,%2,%3}, {%4,%5,%6,%7}, {%8,%9}, {%0,%1,%2,%3};"
        : "+f"(c[0]), "+f"(c[1]), "+f"(c[2]), "+f"(c[3])
        : "r"(a[0]), "r"(a[1]), "r"(a[2]), "r"(a[3]), "r"(b0), "r"(b1));
}
__device__ __forceinline__ void ldsm4(uint32_t& r0, uint32_t& r1, uint32_t& r2, uint32_t& r3,
                                      uint32_t addr) {
    asm volatile("ldmatrix.sync.aligned.m8n8.x4.shared.b16 {%0,%1,%2,%3}, [%4];"
        : "=r"(r0), "=r"(r1), "=r"(r2), "=r"(r3) : "r"(addr));
}

// ---------------- double-buffered cp.async split-bf16 GEMM (R9 + ldmatrix) ----------------
// C = act(A @ B^T + bias) + res ; A,B bf16 hi/lo [*,K] in gmem.
// CTA 128x128, BK=16, 256 thr, 8 warps of 32x64. smem = 2 stages x 24KB = 48KB.
#define ROWU 12
#define TILE_U32 (128*ROWU)            // 1536
#define STAGE_U32 (4*TILE_U32)         // 6144

template<bool RELU>
__global__ void __launch_bounds__(256, 2)
mmgemm_kernel(const __nv_bfloat16* __restrict__ Ahi, const __nv_bfloat16* __restrict__ Alo,
              const __nv_bfloat16* __restrict__ Bhi, const __nv_bfloat16* __restrict__ Blo,
              const float* __restrict__ bias, const float* __restrict__ res,
              float* __restrict__ C,
              __nv_bfloat16* __restrict__ Chi, __nv_bfloat16* __restrict__ Clo,
              int M, int N, int K)
{
    __shared__ uint32_t smem[2 * STAGE_U32];   // 49152 bytes exactly

    const int tid = threadIdx.x;
    const int bm  = blockIdx.y * 128;
    const int bn  = blockIdx.x * 128;
    const int w   = tid >> 5;
    const int l   = tid & 31;
    const int g   = l >> 2;
    const int t   = l & 3;
    const int wm  = (w & 3) * 32;
    const int wn  = (w >> 2) * 64;

    const uint32_t sbase = (uint32_t)__cvta_generic_to_shared(smem);

    float acc[2][8][4];
    #pragma unroll
    for (int i = 0; i < 2; i++)
        #pragma unroll
        for (int j = 0; j < 8; j++)
            #pragma unroll
            for (int e = 0; e < 4; e++) acc[i][j][e] = 0.f;

    const int irow = tid >> 1;
    const int ih   = tid & 1;
    const int am   = bm + irow < M ? bm + irow : M - 1;
    const size_t aoff = (size_t)am * K + ih * 8;
    const size_t boff = (size_t)(bn + irow) * K + ih * 8;

    // ldmatrix per-thread fragment addresses (u32 units within a stage)
    // A frag i: rows wm + i*16 + ((l>>3)&1)*8 + (l&7), u32 col (l>>4)*4
    const int lrow8 = ((l >> 3) & 1) * 8 + (l & 7);
    const int lcol  = (l >> 4) * 4;
    uint32_t aAddr[2];
    #pragma unroll
    for (int i = 0; i < 2; i++)
        aAddr[i] = sbase + (uint32_t)((wm + i * 16 + lrow8) * ROWU + lcol) * 4u;
    // B frag pair jp: rows wn + (2*jp + (l>>4))*8 + (l&7), u32 col ((l>>3)&1)*4
    const int brow = (l >> 4) * 8 + (l & 7);
    const int bcol = ((l >> 3) & 1) * 4;
    uint32_t bAddr[4];
    #pragma unroll
    for (int jp = 0; jp < 4; jp++)
        bAddr[jp] = sbase + (uint32_t)((wn + 2 * jp * 8 + brow) * ROWU + bcol) * 4u;

    const int NS = K >> 4;

    auto issue = [&](int s, int buf) {
        const int k0 = s << 4;
        uint32_t d = sbase + (uint32_t)(buf * STAGE_U32 + irow * ROWU + ih * 4) * 4u;
        cpa16(d,                    Ahi + aoff + k0);
        cpa16(d + TILE_U32*4,       Alo + aoff + k0);
        cpa16(d + 2*TILE_U32*4,     Bhi + boff + k0);
        cpa16(d + 3*TILE_U32*4,     Blo + boff + k0);
        cpa_commit();
    };

    issue(0, 0);

    for (int s = 0; s < NS; s++) {
        const int buf = s & 1;
        if (s + 1 < NS) {
            issue(s + 1, buf ^ 1);
            asm volatile("cp.async.wait_group 1;");
        } else {
            asm volatile("cp.async.wait_group 0;");
        }
        __syncthreads();

        const uint32_t bofs = (uint32_t)(buf * STAGE_U32) * 4u;

        uint32_t ah[2][4], al[2][4];
        #pragma unroll
        for (int i = 0; i < 2; i++) {
            ldsm4(ah[i][0], ah[i][1], ah[i][2], ah[i][3], aAddr[i] + bofs);
            ldsm4(al[i][0], al[i][1], al[i][2], al[i][3], aAddr[i] + bofs + TILE_U32*4);
        }
        #pragma unroll
        for (int jp = 0; jp < 4; jp++) {
            uint32_t bh[4], bl[4];
            ldsm4(bh[0], bh[1], bh[2], bh[3], bAddr[jp] + bofs + 2*TILE_U32*4);
            ldsm4(bl[0], bl[1], bl[2], bl[3], bAddr[jp] + bofs + 3*TILE_U32*4);
            #pragma unroll
            for (int jj = 0; jj < 2; jj++) {
                int j = 2 * jp + jj;
                uint32_t bh0 = bh[2*jj], bh1 = bh[2*jj + 1];
                uint32_t bl0 = bl[2*jj], bl1 = bl[2*jj + 1];
                #pragma unroll
                for (int i = 0; i < 2; i++) {
                    mma16816(acc[i][j], ah[i], bh0, bh1);
                    mma16816(acc[i][j], ah[i], bl0, bl1);
                    mma16816(acc[i][j], al[i], bh0, bh1);
                }
            }
        }
        __syncthreads();
    }

    // ---- epilogue ----
    #pragma unroll
    for (int i = 0; i < 2; i++) {
        #pragma unroll
        for (int half = 0; half < 2; half++) {
            int row = bm + wm + i * 16 + g + half * 8;
            if (row >= M) continue;
            size_t cr = (size_t)row * N;
            #pragma unroll
            for (int j = 0; j < 8; j++) {
                int col = bn + wn + j * 8 + 2 * t;
                float v0 = acc[i][j][half * 2 + 0];
                float v1 = acc[i][j][half * 2 + 1];
                if (bias) { v0 += __ldg(&bias[col]); v1 += __ldg(&bias[col + 1]); }
                if (RELU) { v0 = fmaxf(v0, 0.f); v1 = fmaxf(v1, 0.f); }
                if (res)  { v0 += res[cr + col]; v1 += res[cr + col + 1]; }
                if (C)    *(float2*)&C[cr + col] = make_float2(v0, v1);
                if (Chi) {
                    uint32_t hh, ll; split2(v0, v1, hh, ll);
                    *(uint32_t*)&Chi[cr + col] = hh;
                    *(uint32_t*)&Clo[cr + col] = ll;
                }
            }
        }
    }
}

// ---------------- weight prep: transpose fp32 [K,N] -> bf16 hi/lo [N,K] ----------------
__global__ void wprep_kernel(const float* __restrict__ W,
                             __nv_bfloat16* __restrict__ hi,
                             __nv_bfloat16* __restrict__ lo, int K, int N) {
    __shared__ float t[32][33];
    int n0 = blockIdx.x * 32, k0 = blockIdx.y * 32;
    int tx = threadIdx.x, ty0 = threadIdx.y;
    #pragma unroll
    for (int j = 0; j < 32; j += 8) {
        int ty = ty0 + j;
        t[ty][tx] = W[(size_t)(k0 + ty) * N + n0 + tx];
    }
    __syncthreads();
    #pragma unroll
    for (int j = 0; j < 32; j += 8) {
        int ty = ty0 + j;
        float v = t[tx][ty];
        __nv_bfloat16 h = __float2bfloat16(v);
        size_t o = (size_t)(n0 + ty) * K + k0 + tx;
        hi[o] = h;
        lo[o] = __float2bfloat16(v - __bfloat162float(h));
    }
}

// split fp32 -> bf16 hi/lo, no transpose (vectorized)
__global__ void wsplit_kernel(const float* __restrict__ W,
                              __nv_bfloat16* __restrict__ hi,
                              __nv_bfloat16* __restrict__ lo, int n) {
    int i = (blockIdx.x * blockDim.x + threadIdx.x) * 2;
    if (i < n) {
        float2 v = *(const float2*)(W + i);
        uint32_t hh, ll;
        split2(v.x, v.y, hh, ll);
        *(uint32_t*)&hi[i] = hh;
        *(uint32_t*)&lo[i] = ll;
    }
}

// transpose Ut[d][r] -> U[r][d] fp32 + bf16 hi/lo split
__global__ void utsplit_kernel() {
    __shared__ float tb[32][33];
    int r0 = blockIdx.x * 32, d0 = blockIdx.y * 32;
    int tx = threadIdx.x, ty0 = threadIdx.y;
    #pragma unroll
    for (int j = 0; j < 32; j += 8) {
        int d = d0 + ty0 + j, r = r0 + tx;
        tb[ty0 + j][tx] = (r < RT) ? g_Ut[(size_t)d * RT + r] : 0.f;
    }
    __syncthreads();
    #pragma unroll
    for (int j = 0; j < 32; j += 8) {
        int r = r0 + ty0 + j, d = d0 + tx;
        if (r < RT) {
            float v = tb[tx][ty0 + j];
            size_t o = (size_t)r * Dk + d;
            g_U[o] = v;
            __nv_bfloat16 h = __float2bfloat16(v);
            g_U_h[o] = h;
            g_U_l[o] = __float2bfloat16(v - __bfloat162float(h));
        }
    }
}

// ---------------- twiddle init ----------------
__global__ void init_tw_kernel() {
    int k = blockIdx.x * blockDim.x + threadIdx.x;
    if (k < Lk/2) {
        double ang = -2.0 * PI_D * (double)k / (double)Lk;
        g_tw[k] = make_float2((float)cos(ang), (float)sin(ang));
    }
}

// ---------------- FFT core ----------------
__device__ __forceinline__ void fft_core(float2* s) {
    for (int len = 2; len <= Lk; len <<= 1) {
        int half = len >> 1;
        int lh   = __ffs(half) - 1;
        int tws  = Lk / len;
        for (int j = threadIdx.x; j < Lk/2; j += blockDim.x) {
            int k  = j & (half - 1);
            int g  = j >> lh;
            int i0 = g * len + k;
            int i1 = i0 + half;
            float2 w = g_tw[k * tws];
            float2 a = s[i0], b = s[i1];
            float tre = w.x * b.x - w.y * b.y;
            float tim = w.x * b.y + w.y * b.x;
            s[i1] = make_float2(a.x - tre, a.y - tim);
            s[i0] = make_float2(a.x + tre, a.y + tim);
        }
        __syncthreads();
    }
}

// forward FFT of x, writes transposed spectrum Ut[d][r] (coalesced)
__global__ void fft_x_kernel(const float* __restrict__ x) {
    __shared__ float2 s[Lk];
    int b  = blockIdx.x;
    int pr = blockIdx.y;
    int d0 = 2 * pr, d1 = d0 + 1;
    const float* xb = x + (size_t)b * Lk * Dk;
    for (int t = threadIdx.x; t < Lk; t += blockDim.x) {
        int r = __brev((unsigned)t) >> (32 - 12);
        s[r] = make_float2(xb[(size_t)t * Dk + d0], xb[(size_t)t * Dk + d1]);
    }
    __syncthreads();
    fft_core(s);
    const int BNF = Bk * NFk;
    float* u0re = g_Ut + (size_t)d0 * RT + b * NFk;
    float* u0im = u0re + BNF;
    float* u1re = g_Ut + (size_t)d1 * RT + b * NFk;
    float* u1im = u1re + BNF;
    for (int f = threadIdx.x; f <= Lk/2; f += blockDim.x) {
        float2 zf = s[f];
        float2 zn = s[(Lk - f) & (Lk - 1)];
        u0re[f] = 0.5f * (zf.x + zn.x);
        u0im[f] = 0.5f * (zf.y - zn.y);
        u1re[f] = 0.5f * (zf.y + zn.y);
        u1im[f] = 0.5f * (zn.x - zf.x);
    }
}

// S[b,f] = VU[b,f,:] . conj(U[b,f,:])
__global__ void sreduce_kernel() {
    int row = blockIdx.x;
    const float* vre = g_VU + (size_t)row * Dk;
    const float* vim = g_VU + ((size_t)(Bk*NFk) + row) * Dk;
    const float* ure = g_U  + (size_t)row * Dk;
    const float* uim = g_U  + ((size_t)(Bk*NFk) + row) * Dk;
    float sre = 0.f, sim = 0.f;
    for (int d = threadIdx.x; d < Dk; d += blockDim.x) {
        float vr = vre[d], vi = vim[d], ur = ure[d], ui = uim[d];
        sre += vr * ur + vi * ui;
        sim += vi * ur - vr * ui;
    }
    __shared__ float rre[128], rim[128];
    int tid = threadIdx.x;
    rre[tid] = sre; rim[tid] = sim;
    __syncthreads();
    for (int st = 64; st > 0; st >>= 1) {
        if (tid < st) { rre[tid] += rre[tid + st]; rim[tid] += rim[tid + st]; }
        __syncthreads();
    }
    if (tid == 0) g_S[row] = make_float2(rre[0], rim[0]);
}

// exact fp32 S at f=0
__global__ void s0fix_kernel(const float* __restrict__ Wq, const float* __restrict__ bq,
                             const float* __restrict__ Wk, const float* __restrict__ bk) {
    int b = blockIdx.x;
    int i = threadIdx.x;
    __shared__ float u0[Dk];
    const float* ur = g_U + (size_t)(b * NFk) * Dk;
    u0[i] = ur[i];
    __syncthreads();
    float q = 0.f, k = 0.f;
    for (int t = 0; t < Dk; t++) {
        float u = u0[t];
        q += u * Wq[(size_t)t * Dk + i];
        k += u * Wk[(size_t)t * Dk + i];
    }
    q += (float)Lk * bq[i];
    k += (float)Lk * bk[i];
    __shared__ float red[Dk];
    red[i] = q * k;
    __syncthreads();
    for (int st = 256; st > 0; st >>= 1) {
        if (i < st) red[i] += red[i + st];
        __syncthreads();
    }
    if (i == 0) g_S[b * NFk] = make_float2(red[0], 0.f);
}

__global__ void ifft_corr_kernel() {
    __shared__ float2 s[Lk];
    int b = blockIdx.x;
    for (int f = threadIdx.x; f < Lk; f += blockDim.x) {
        float2 v;
        if (f <= Lk/2) { float2 sf = g_S[b * NFk + f]; v = make_float2(sf.x, -sf.y); }
        else           { v = g_S[b * NFk + (Lk - f)]; }
        int r = __brev((unsigned)f) >> (32 - 12);
        s[r] = v;
    }
    __syncthreads();
    fft_core(s);
    float scale = 1.0f / ((float)Lk * (float)Dk);
    for (int t = threadIdx.x; t < Lk; t += blockDim.x)
        g_corr[b * Lk + t] = s[t].x * scale;
}

// top-8 + softmax
__global__ void topk_kernel() {
    int b = blockIdx.x;
    const float* c = g_corr + b * Lk;
    __shared__ float sv[256];
    __shared__ int   si[256];
    __shared__ int   ch_i[KTOP];
    __shared__ float ch_v[KTOP];
    int tid = threadIdx.x;
    for (int it = 0; it < KTOP; it++) {
        float bv = -3.402823e38f; int bi = 0x7fffffff;
        for (int t = tid; t < Lk; t += 256) {
            bool skip = false;
            for (int q = 0; q < it; q++) if (ch_i[q] == t) skip = true;
            if (skip) continue;
            float v = c[t];
            if (v > bv || (v == bv && t < bi)) { bv = v; bi = t; }
        }
        sv[tid] = bv; si[tid] = bi;
        __syncthreads();
        for (int st = 128; st > 0; st >>= 1) {
            if (tid < st) {
                if (sv[tid+st] > sv[tid] || (sv[tid+st] == sv[tid] && si[tid+st] < si[tid])) {
                    sv[tid] = sv[tid+st]; si[tid] = si[tid+st];
                }
            }
            __syncthreads();
        }
        if (tid == 0) { ch_i[it] = si[0]; ch_v[it] = sv[0]; }
        __syncthreads();
    }
    if (tid == 0) {
        float m = ch_v[0];
        for (int q = 1; q < KTOP; q++) m = fmaxf(m, ch_v[q]);
        float e[KTOP]; float sum = 0.f;
        for (int q = 0; q < KTOP; q++) { e[q] = expf(ch_v[q] - m); sum += e[q]; }
        for (int q = 0; q < KTOP; q++) {
            g_p[b*KTOP+q]     = e[q] / sum;
            g_delay[b*KTOP+q] = ch_i[q];
        }
    }
}

// attn (bf16 hi/lo) = sum_j p_j * V[b,(t+delay_j)%L,:]
__global__ void gather_kernel() {
    int bt = blockIdx.x;
    int b = bt >> 12, t = bt & (Lk - 1);
    __shared__ float pp[KTOP];
    __shared__ int   dd[KTOP];
    if (threadIdx.x < KTOP) {
        pp[threadIdx.x] = g_p[b*KTOP + threadIdx.x];
        dd[threadIdx.x] = g_delay[b*KTOP + threadIdx.x];
    }
    __syncthreads();
    int d = threadIdx.x * 4;
    float4 acc = make_float4(0.f, 0.f, 0.f, 0.f);
    #pragma unroll
    for (int j = 0; j < KTOP; j++) {
        int src = (t + dd[j]) & (Lk - 1);
        float4 v = *(const float4*)&g_V[(((size_t)b * Lk) + src) * Dk + d];
        acc.x += pp[j] * v.x; acc.y += pp[j] * v.y;
        acc.z += pp[j] * v.z; acc.w += pp[j] * v.w;
    }
    size_t o = (size_t)bt * Dk + d;
    uint32_t h0, l0, h1, l1;
    split2(acc.x, acc.y, h0, l0);
    split2(acc.z, acc.w, h1, l1);
    *(uint2*)&g_at_h[o] = make_uint2(h0, h1);
    *(uint2*)&g_at_l[o] = make_uint2(l0, l1);
}

// out = h - avgpool_same(h,25); optional bf16 hi/lo copy. chunk=64 rows/block.
__global__ void pool_kernel(const float* __restrict__ h, float* __restrict__ out,
                            __nv_bfloat16* __restrict__ oh, __nv_bfloat16* __restrict__ ol) {
    int b  = blockIdx.y;
    int t0 = blockIdx.x * 64;
    int d  = threadIdx.x;
    const float* hb = h   + (size_t)b * Lk * Dk + d;
    float*       ob = out + (size_t)b * Lk * Dk + d;
    float sum = 0.f;
    int lo = t0 - 12 < 0 ? 0 : t0 - 12;
    int hi = t0 + 12 > Lk - 1 ? Lk - 1 : t0 + 12;
    for (int t = lo; t <= hi; t++) sum += hb[(size_t)t * Dk];
    for (int t = t0; t < t0 + 64; t++) {
        int wlo = t - 12 < 0 ? 0 : t - 12;
        int whi = t + 12 > Lk - 1 ? Lk - 1 : t + 12;
        float cnt = (float)(whi - wlo + 1);
        float v = hb[(size_t)t * Dk] - sum / cnt;
        ob[(size_t)t * Dk] = v;
        if (oh) {
            size_t o = ((size_t)b * Lk + t) * Dk + d;
            __nv_bfloat16 hh = __float2bfloat16(v);
            oh[o] = hh;
            ol[o] = __float2bfloat16(v - __bfloat162float(hh));
        }
        int add = t + 13; if (add < Lk)  sum += hb[(size_t)add * Dk];
        int rem = t - 12; if (rem >= 0)  sum -= hb[(size_t)rem * Dk];
    }
}

// ---------------- launch ----------------
extern "C" void kernel_launch(void* const* d_in, const int* in_sizes, int n_in,
                              void* d_out, int out_size) {
    const float* x  = (const float*)d_in[0];
    const float* Wq = (const float*)d_in[1];
    const float* bq = (const float*)d_in[2];
    const float* Wk = (const float*)d_in[3];
    const float* bk = (const float*)d_in[4];
    const float* Wv = (const float*)d_in[5];
    const float* bv = (const float*)d_in[6];
    const float* Wo = (const float*)d_in[7];
    const float* bo = (const float*)d_in[8];
    const float* W1 = (const float*)d_in[9];
    const float* b1 = (const float*)d_in[10];
    const float* W2 = (const float*)d_in[11];
    const float* b2 = (const float*)d_in[12];
    float* out = (float*)d_out;

    float *pV, *pVU, *ph, *pS1, *ph2, *pG;
    __nv_bfloat16 *pxh,*pxl,*pUh,*pUl,*path,*patl,*pS1h,*pS1l,*phidh,*phidl;
    __nv_bfloat16 *pWvt_h,*pWvt_l,*pWot_h,*pWot_l,*pW1t_h,*pW1t_l,*pW2t_h,*pW2t_l;
    __nv_bfloat16 *pWq_h,*pWq_l,*pWk_h,*pWk_l,*pGt_h,*pGt_l;
    cudaGetSymbolAddress((void**)&pV,    g_V);
    cudaGetSymbolAddress((void**)&pVU,   g_VU);
    cudaGetSymbolAddress((void**)&ph,    g_h);
    cudaGetSymbolAddress((void**)&pS1,   g_S1);
    cudaGetSymbolAddress((void**)&ph2,   g_h2);
    cudaGetSymbolAddress((void**)&pG,    g_G);
    cudaGetSymbolAddress((void**)&pxh,   g_x_h);   cudaGetSymbolAddress((void**)&pxl,   g_x_l);
    cudaGetSymbolAddress((void**)&pUh,   g_U_h);   cudaGetSymbolAddress((void**)&pUl,   g_U_l);
    cudaGetSymbolAddress((void**)&path,  g_at_h);  cudaGetSymbolAddress((void**)&patl,  g_at_l);
    cudaGetSymbolAddress((void**)&pS1h,  g_S1_h);  cudaGetSymbolAddress((void**)&pS1l,  g_S1_l);
    cudaGetSymbolAddress((void**)&phidh, g_hid_h); cudaGetSymbolAddress((void**)&phidl, g_hid_l);
    cudaGetSymbolAddress((void**)&pWvt_h, g_Wvt_h); cudaGetSymbolAddress((void**)&pWvt_l, g_Wvt_l);
    cudaGetSymbolAddress((void**)&pWot_h, g_Wot_h); cudaGetSymbolAddress((void**)&pWot_l, g_Wot_l);
    cudaGetSymbolAddress((void**)&pW1t_h, g_W1t_h); cudaGetSymbolAddress((void**)&pW1t_l, g_W1t_l);
    cudaGetSymbolAddress((void**)&pW2t_h, g_W2t_h); cudaGetSymbolAddress((void**)&pW2t_l, g_W2t_l);
    cudaGetSymbolAddress((void**)&pWq_h,  g_Wq_h);  cudaGetSymbolAddress((void**)&pWq_l,  g_Wq_l);
    cudaGetSymbolAddress((void**)&pWk_h,  g_Wk_h);  cudaGetSymbolAddress((void**)&pWk_l,  g_Wk_l);
    cudaGetSymbolAddress((void**)&pGt_h,  g_Gt_h);  cudaGetSymbolAddress((void**)&pGt_l,  g_Gt_l);

    const int MR = Bk * Lk;              // 16384
    const int MUt = (RT + 127) / 128;    // 129
    dim3 wb(32, 8);

    init_tw_kernel<<<(Lk/2 + 255)/256, 256>>>();                                     // 1
    wprep_kernel<<<dim3(Dk/32,  Dk/32),  wb>>>(Wv, pWvt_h, pWvt_l, Dk, Dk);          // 2
    wsplit_kernel<<<(MR*Dk/2 + 255)/256, 256>>>(x, pxh, pxl, MR*Dk);                 // 3
    mmgemm_kernel<false><<<dim3(Dk/128, MR/128), 256>>>(                             // 4: V = x@Wv + bv
        pxh, pxl, pWvt_h, pWvt_l, bv, nullptr, pV, nullptr, nullptr, MR, Dk, Dk);
    fft_x_kernel<<<dim3(Bk, Dk/2), 512>>>(x);                                        // 5
    utsplit_kernel<<<dim3((RT + 31)/32, Dk/32), wb>>>();                             // 6
    wsplit_kernel<<<(Dk*Dk/2 + 255)/256, 256>>>(Wq, pWq_h, pWq_l, Dk*Dk);            // 7
    wsplit_kernel<<<(Dk*Dk/2 + 255)/256, 256>>>(Wk, pWk_h, pWk_l, Dk*Dk);            // 8
    mmgemm_kernel<false><<<dim3(Dk/128, Dk/128), 256>>>(                             // 9: G = Wq@Wk^T
        pWq_h, pWq_l, pWk_h, pWk_l, nullptr, nullptr, pG, nullptr, nullptr, Dk, Dk, Dk);
    wprep_kernel<<<dim3(Dk/32, Dk/32), wb>>>(pG, pGt_h, pGt_l, Dk, Dk);              // 10
    mmgemm_kernel<false><<<dim3(Dk/128, MUt), 256>>>(                                // 11: VU = U@G
        pUh, pUl, pGt_h, pGt_l, nullptr, nullptr, pVU, nullptr, nullptr, RT, Dk, Dk);
    sreduce_kernel<<<Bk * NFk, 128>>>();                                             // 12
    s0fix_kernel<<<Bk, Dk>>>(Wq, bq, Wk, bk);                                        // 13
    ifft_corr_kernel<<<Bk, 512>>>();                                                 // 14
    topk_kernel<<<Bk, 256>>>();                                                      // 15
    gather_kernel<<<Bk * Lk, 128>>>();                                               // 16
    wprep_kernel<<<dim3(Dk/32, Dk/32), wb>>>(Wo, pWot_h, pWot_l, Dk, Dk);            // 17
    mmgemm_kernel<false><<<dim3(Dk/128, MR/128), 256>>>(                             // 18: h = attn@Wo + bo + x
        path, patl, pWot_h, pWot_l, bo, x, ph, nullptr, nullptr, MR, Dk, Dk);
    pool_kernel<<<dim3(Lk/64, Bk), 512>>>(ph, pS1, pS1h, pS1l);                      // 19
    wprep_kernel<<<dim3(DFFk/32, Dk/32), wb>>>(W1, pW1t_h, pW1t_l, Dk, DFFk);        // 20
    mmgemm_kernel<true><<<dim3(DFFk/128, MR/128), 256>>>(                            // 21: hid = relu(S1@W1+b1)
        pS1h, pS1l, pW1t_h, pW1t_l, b1, nullptr, nullptr, phidh, phidl, MR, DFFk, Dk);
    wprep_kernel<<<dim3(Dk/32, DFFk/32), wb>>>(W2, pW2t_h, pW2t_l, DFFk, Dk);        // 22
    mmgemm_kernel<true><<<dim3(Dk/128, MR/128), 256>>>(                              // 23: h2 = relu(hid@W2+b2)+S1
        phidh, phidl, pW2t_h, pW2t_l, b2, pS1, ph2, nullptr, nullptr, MR, Dk, DFFk);
    pool_kernel<<<dim3(Lk/64, Bk), 512>>>(ph2, out, nullptr, nullptr);               // 24
}

// round 12
// speedup vs baseline: 1.0026x; 1.0026x over previous
#include <cuda_runtime.h>
#include <cuda_bf16.h>
#include <math.h>
#include <stdint.h>

#define Bk   4
#define Lk   4096
#define Dk   512
#define DFFk 2048
#define NFk  2049          // rfft bins = L/2+1
#define KTOP 8
#define PI_D 3.14159265358979323846
#define RT   (2*Bk*NFk)    // 16392 spectrum rows (re block ; im block)

// ---------------- scratch (static device globals; no allocation) ----------------
__device__ float  g_V    [Bk*Lk*Dk];
__device__ float  g_Ut   [(size_t)Dk*RT];   // transposed spectrum [d][r]
__device__ float  g_U    [(size_t)RT*Dk];   // [r][d] fp32
__device__ float  g_VU   [(size_t)RT*Dk];   // U @ G
__device__ float2 g_S    [Bk*NFk];
__device__ float  g_corr [Bk*Lk];
__device__ int    g_delay[Bk*KTOP];
__device__ float  g_p    [Bk*KTOP];
__device__ float  g_h    [Bk*Lk*Dk];
__device__ float  g_S1   [Bk*Lk*Dk];
__device__ float  g_h2   [Bk*Lk*Dk];
__device__ float2 g_tw   [Lk/2];
__device__ float  g_G    [Dk*Dk];

// bf16 hi/lo activations (A operands)
__device__ __nv_bfloat16 g_x_h  [Bk*Lk*Dk],    g_x_l  [Bk*Lk*Dk];
__device__ __nv_bfloat16 g_U_h  [(size_t)RT*Dk], g_U_l[(size_t)RT*Dk];
__device__ __nv_bfloat16 g_at_h [Bk*Lk*Dk],    g_at_l [Bk*Lk*Dk];
__device__ __nv_bfloat16 g_S1_h [Bk*Lk*Dk],    g_S1_l [Bk*Lk*Dk];
__device__ __nv_bfloat16 g_hid_h[(size_t)Bk*Lk*DFFk], g_hid_l[(size_t)Bk*Lk*DFFk];

// bf16 split weights ([N,K] layout for mma B operand = W^T)
__device__ __nv_bfloat16 g_Wvt_h[Dk*Dk],  g_Wvt_l[Dk*Dk];
__device__ __nv_bfloat16 g_Wot_h[Dk*Dk],  g_Wot_l[Dk*Dk];
__device__ __nv_bfloat16 g_W1t_h[DFFk*Dk],g_W1t_l[DFFk*Dk];
__device__ __nv_bfloat16 g_W2t_h[Dk*DFFk],g_W2t_l[Dk*DFFk];
__device__ __nv_bfloat16 g_Wq_h [Dk*Dk],  g_Wq_l [Dk*Dk];
__device__ __nv_bfloat16 g_Wk_h [Dk*Dk],  g_Wk_l [Dk*Dk];
__device__ __nv_bfloat16 g_Gt_h [Dk*Dk],  g_Gt_l [Dk*Dk];

// ---------------- helpers ----------------
__device__ __forceinline__ void split2(float v0, float v1, uint32_t& hi, uint32_t& lo) {
    __nv_bfloat162 h = __floats2bfloat162_rn(v0, v1);
    float2 f = __bfloat1622float2(h);
    __nv_bfloat162 l = __floats2bfloat162_rn(v0 - f.x, v1 - f.y);
    hi = *(uint32_t*)&h; lo = *(uint32_t*)&l;
}
__device__ __forceinline__ void cpa16(uint32_t dst, const void* src) {
    asm volatile("cp.async.cg.shared.global [%0], [%1], 16;" :: "r"(dst), "l"(src));
}
__device__ __forceinline__ void cpa_commit() { asm volatile("cp.async.commit_group;"); }
__device__ __forceinline__ void mma16816(float* c, const uint32_t* a,
                                         uint32_t b0, uint32_t b1) {
    asm volatile(
        "mma.sync.aligned.m16n8k16.row.col.f32.bf16.bf16.f32 "
        "{%0,%1,%2,%3}, {%4,%5,%6,%7}, {%8,%9}, {%0,%1,%2,%3};"
        : "+f"(c[0]), "+f"(c[1]), "+f"(c[2]), "+f"(c[3])
        : "r"(a[0]), "r"(a[1]), "r"(a[2]), "r"(a[3]), "r"(b0), "r"(b1));
}
__device__ __forceinline__ void ldsm4(uint32_t& r0, uint32_t& r1, uint32_t& r2, uint32_t& r3,
                                      uint32_t addr) {
    asm volatile("ldmatrix.sync.aligned.m8n8.x4.shared.b16 {%0,%1,%2,%3}, [%4];"
        : "=r"(r0), "=r"(r1), "=r"(r2), "=r"(r3) : "r"(addr));
}

// ---------------- double-buffered cp.async split-bf16 GEMM (R9 + ldmatrix) ----------------
// C = act(A @ B^T + bias) + res ; A,B bf16 hi/lo [*,K] in gmem.
// CTA 128x128, BK=16, 256 thr, 8 warps of 32x64. smem = 2 stages x 24KB = 48KB.
#define ROWU 12
#define TILE_U32 (128*ROWU)            // 1536
#define STAGE_U32 (4*TILE_U32)         // 6144

template<bool RELU>
__global__ void __launch_bounds__(256, 2)
mmgemm_kernel(const __nv_bfloat16* __restrict__ Ahi, const __nv_bfloat16* __restrict__ Alo,
              const __nv_bfloat16* __restrict__ Bhi, const __nv_bfloat16* __restrict__ Blo,
              const float* __restrict__ bias, const float* __restrict__ res,
              float* __restrict__ C,
              __nv_bfloat16* __restrict__ Chi, __nv_bfloat16* __restrict__ Clo,
              int M, int N, int K)
{
    __shared__ uint32_t smem[2 * STAGE_U32];   // 49152 bytes exactly

    const int tid = threadIdx.x;
    const int bm  = blockIdx.y * 128;
    const int bn  = blockIdx.x * 128;
    const int w   = tid >> 5;
    const int l   = tid & 31;
    const int g   = l >> 2;
    const int t   = l & 3;
    const int wm  = (w & 3) * 32;
    const int wn  = (w >> 2) * 64;

    const uint32_t sbase = (uint32_t)__cvta_generic_to_shared(smem);

    float acc[2][8][4];
    #pragma unroll
    for (int i = 0; i < 2; i++)
        #pragma unroll
        for (int j = 0; j < 8; j++)
            #pragma unroll
            for (int e = 0; e < 4; e++) acc[i][j][e] = 0.f;

    const int irow = tid >> 1;
    const int ih   = tid & 1;
    const int am   = bm + irow < M ? bm + irow : M - 1;
    const size_t aoff = (size_t)am * K + ih * 8;
    const size_t boff = (size_t)(bn + irow) * K + ih * 8;

    // ldmatrix per-thread fragment addresses (u32 units within a stage)
    // A frag i: rows wm + i*16 + ((l>>3)&1)*8 + (l&7), u32 col (l>>4)*4
    const int lrow8 = ((l >> 3) & 1) * 8 + (l & 7);
    const int lcol  = (l >> 4) * 4;
    uint32_t aAddr[2];
    #pragma unroll
    for (int i = 0; i < 2; i++)
        aAddr[i] = sbase + (uint32_t)((wm + i * 16 + lrow8) * ROWU + lcol) * 4u;
    // B frag pair jp: rows wn + (2*jp + (l>>4))*8 + (l&7), u32 col ((l>>3)&1)*4
    const int brow = (l >> 4) * 8 + (l & 7);
    const int bcol = ((l >> 3) & 1) * 4;
    uint32_t bAddr[4];
    #pragma unroll
    for (int jp = 0; jp < 4; jp++)
        bAddr[jp] = sbase + (uint32_t)((wn + 2 * jp * 8 + brow) * ROWU + bcol) * 4u;

    const int NS = K >> 4;

    auto issue = [&](int s, int buf) {
        const int k0 = s << 4;
        uint32_t d = sbase + (uint32_t)(buf * STAGE_U32 + irow * ROWU + ih * 4) * 4u;
        cpa16(d,                    Ahi + aoff + k0);
        cpa16(d + TILE_U32*4,       Alo + aoff + k0);
        cpa16(d + 2*TILE_U32*4,     Bhi + boff + k0);
        cpa16(d + 3*TILE_U32*4,     Blo + boff + k0);
        cpa_commit();
    };

    issue(0, 0);

    for (int s = 0; s < NS; s++) {
        const int buf = s & 1;
        if (s + 1 < NS) {
            issue(s + 1, buf ^ 1);
            asm volatile("cp.async.wait_group 1;");
        } else {
            asm volatile("cp.async.wait_group 0;");
        }
        __syncthreads();

        const uint32_t bofs = (uint32_t)(buf * STAGE_U32) * 4u;

        uint32_t ah[2][4], al[2][4];
        #pragma unroll
        for (int i = 0; i < 2; i++) {
            ldsm4(ah[i][0], ah[i][1], ah[i][2], ah[i][3], aAddr[i] + bofs);
            ldsm4(al[i][0], al[i][1], al[i][2], al[i][3], aAddr[i] + bofs + TILE_U32*4);
        }
        #pragma unroll
        for (int jp = 0; jp < 4; jp++) {
            uint32_t bh[4], bl[4];
            ldsm4(bh[0], bh[1], bh[2], bh[3], bAddr[jp] + bofs + 2*TILE_U32*4);
            ldsm4(bl[0], bl[1], bl[2], bl[3], bAddr[jp] + bofs + 3*TILE_U32*4);
            #pragma unroll
            for (int jj = 0; jj < 2; jj++) {
                int j = 2 * jp + jj;
                uint32_t bh0 = bh[2*jj], bh1 = bh[2*jj + 1];
                uint32_t bl0 = bl[2*jj], bl1 = bl[2*jj + 1];
                #pragma unroll
                for (int i = 0; i < 2; i++) {
                    mma16816(acc[i][j], ah[i], bh0, bh1);
                    mma16816(acc[i][j], ah[i], bl0, bl1);
                    mma16816(acc[i][j], al[i], bh0, bh1);
                }
            }
        }
        __syncthreads();
    }

    // ---- epilogue ----
    #pragma unroll
    for (int i = 0; i < 2; i++) {
        #pragma unroll
        for (int half = 0; half < 2; half++) {
            int row = bm + wm + i * 16 + g + half * 8;
            if (row >= M) continue;
            size_t cr = (size_t)row * N;
            #pragma unroll
            for (int j = 0; j < 8; j++) {
                int col = bn + wn + j * 8 + 2 * t;
                float v0 = acc[i][j][half * 2 + 0];
                float v1 = acc[i][j][half * 2 + 1];
                if (bias) { v0 += __ldg(&bias[col]); v1 += __ldg(&bias[col + 1]); }
                if (RELU) { v0 = fmaxf(v0, 0.f); v1 = fmaxf(v1, 0.f); }
                if (res)  { v0 += res[cr + col]; v1 += res[cr + col + 1]; }
                if (C)    *(float2*)&C[cr + col] = make_float2(v0, v1);
                if (Chi) {
                    uint32_t hh, ll; split2(v0, v1, hh, ll);
                    *(uint32_t*)&Chi[cr + col] = hh;
                    *(uint32_t*)&Clo[cr + col] = ll;
                }
            }
        }
    }
}

// ---------------- weight prep: transpose fp32 [K,N] -> bf16 hi/lo [N,K] ----------------
__global__ void wprep_kernel(const float* __restrict__ W,
                             __nv_bfloat16* __restrict__ hi,
                             __nv_bfloat16* __restrict__ lo, int K, int N) {
    __shared__ float t[32][33];
    int n0 = blockIdx.x * 32, k0 = blockIdx.y * 32;
    int tx = threadIdx.x, ty0 = threadIdx.y;
    #pragma unroll
    for (int j = 0; j < 32; j += 8) {
        int ty = ty0 + j;
        t[ty][tx] = W[(size_t)(k0 + ty) * N + n0 + tx];
    }
    __syncthreads();
    #pragma unroll
    for (int j = 0; j < 32; j += 8) {
        int ty = ty0 + j;
        float v = t[tx][ty];
        __nv_bfloat16 h = __float2bfloat16(v);
        size_t o = (size_t)(n0 + ty) * K + k0 + tx;
        hi[o] = h;
        lo[o] = __float2bfloat16(v - __bfloat162float(h));
    }
}

// split fp32 -> bf16 hi/lo, no transpose (vectorized)
__global__ void wsplit_kernel(const float* __restrict__ W,
                              __nv_bfloat16* __restrict__ hi,
                              __nv_bfloat16* __restrict__ lo, int n) {
    int i = (blockIdx.x * blockDim.x + threadIdx.x) * 2;
    if (i < n) {
        float2 v = *(const float2*)(W + i);
        uint32_t hh, ll;
        split2(v.x, v.y, hh, ll);
        *(uint32_t*)&hi[i] = hh;
        *(uint32_t*)&lo[i] = ll;
    }
}

// transpose Ut[d][r] -> U[r][d] fp32 + bf16 hi/lo split
__global__ void utsplit_kernel() {
    __shared__ float tb[32][33];
    int r0 = blockIdx.x * 32, d0 = blockIdx.y * 32;
    int tx = threadIdx.x, ty0 = threadIdx.y;
    #pragma unroll
    for (int j = 0; j < 32; j += 8) {
        int d = d0 + ty0 + j, r = r0 + tx;
        tb[ty0 + j][tx] = (r < RT) ? g_Ut[(size_t)d * RT + r] : 0.f;
    }
    __syncthreads();
    #pragma unroll
    for (int j = 0; j < 32; j += 8) {
        int r = r0 + ty0 + j, d = d0 + tx;
        if (r < RT) {
            float v = tb[tx][ty0 + j];
            size_t o = (size_t)r * Dk + d;
            g_U[o] = v;
            __nv_bfloat16 h = __float2bfloat16(v);
            g_U_h[o] = h;
            g_U_l[o] = __float2bfloat16(v - __bfloat162float(h));
        }
    }
}

// ---------------- twiddle init ----------------
__global__ void init_tw_kernel() {
    int k = blockIdx.x * blockDim.x + threadIdx.x;
    if (k < Lk/2) {
        double ang = -2.0 * PI_D * (double)k / (double)Lk;
        g_tw[k] = make_float2((float)cos(ang), (float)sin(ang));
    }
}

// ---------------- FFT core ----------------
__device__ __forceinline__ void fft_core(float2* s) {
    for (int len = 2; len <= Lk; len <<= 1) {
        int half = len >> 1;
        int lh   = __ffs(half) - 1;
        int tws  = Lk / len;
        for (int j = threadIdx.x; j < Lk/2; j += blockDim.x) {
            int k  = j & (half - 1);
            int g  = j >> lh;
            int i0 = g * len + k;
            int i1 = i0 + half;
            float2 w = g_tw[k * tws];
            float2 a = s[i0], b = s[i1];
            float tre = w.x * b.x - w.y * b.y;
            float tim = w.x * b.y + w.y * b.x;
            s[i1] = make_float2(a.x - tre, a.y - tim);
            s[i0] = make_float2(a.x + tre, a.y + tim);
        }
        __syncthreads();
    }
}

// forward FFT of x, writes transposed spectrum Ut[d][r] (coalesced)
__global__ void fft_x_kernel(const float* __restrict__ x) {
    __shared__ float2 s[Lk];
    int b  = blockIdx.x;
    int pr = blockIdx.y;
    int d0 = 2 * pr, d1 = d0 + 1;
    const float* xb = x + (size_t)b * Lk * Dk;
    for (int t = threadIdx.x; t < Lk; t += blockDim.x) {
        int r = __brev((unsigned)t) >> (32 - 12);
        s[r] = make_float2(xb[(size_t)t * Dk + d0], xb[(size_t)t * Dk + d1]);
    }
    __syncthreads();
    fft_core(s);
    const int BNF = Bk * NFk;
    float* u0re = g_Ut + (size_t)d0 * RT + b * NFk;
    float* u0im = u0re + BNF;
    float* u1re = g_Ut + (size_t)d1 * RT + b * NFk;
    float* u1im = u1re + BNF;
    for (int f = threadIdx.x; f <= Lk/2; f += blockDim.x) {
        float2 zf = s[f];
        float2 zn = s[(Lk - f) & (Lk - 1)];
        u0re[f] = 0.5f * (zf.x + zn.x);
        u0im[f] = 0.5f * (zf.y - zn.y);
        u1re[f] = 0.5f * (zf.y + zn.y);
        u1im[f] = 0.5f * (zn.x - zf.x);
    }
}

// S[b,f] = VU[b,f,:] . conj(U[b,f,:])
__global__ void sreduce_kernel() {
    int row = blockIdx.x;
    const float* vre = g_VU + (size_t)row * Dk;
    const float* vim = g_VU + ((size_t)(Bk*NFk) + row) * Dk;
    const float* ure = g_U  + (size_t)row * Dk;
    const float* uim = g_U  + ((size_t)(Bk*NFk) + row) * Dk;
    float sre = 0.f, sim = 0.f;
    for (int d = threadIdx.x; d < Dk; d += blockDim.x) {
        float vr = vre[d], vi = vim[d], ur = ure[d], ui = uim[d];
        sre += vr * ur + vi * ui;
        sim += vi * ur - vr * ui;
    }
    __shared__ float rre[128], rim[128];
    int tid = threadIdx.x;
    rre[tid] = sre; rim[tid] = sim;
    __syncthreads();
    for (int st = 64; st > 0; st >>= 1) {
        if (tid < st) { rre[tid] += rre[tid + st]; rim[tid] += rim[tid + st]; }
        __syncthreads();
    }
    if (tid == 0) g_S[row] = make_float2(rre[0], rim[0]);
}

// exact fp32 S at f=0
__global__ void s0fix_kernel(const float* __restrict__ Wq, const float* __restrict__ bq,
                             const float* __restrict__ Wk, const float* __restrict__ bk) {
    int b = blockIdx.x;
    int i = threadIdx.x;
    __shared__ float u0[Dk];
    const float* ur = g_U + (size_t)(b * NFk) * Dk;
    u0[i] = ur[i];
    __syncthreads();
    float q = 0.f, k = 0.f;
    for (int t = 0; t < Dk; t++) {
        float u = u0[t];
        q += u * Wq[(size_t)t * Dk + i];
        k += u * Wk[(size_t)t * Dk + i];
    }
    q += (float)Lk * bq[i];
    k += (float)Lk * bk[i];
    __shared__ float red[Dk];
    red[i] = q * k;
    __syncthreads();
    for (int st = 256; st > 0; st >>= 1) {
        if (i < st) red[i] += red[i + st];
        __syncthreads();
    }
    if (i == 0) g_S[b * NFk] = make_float2(red[0], 0.f);
}

__global__ void ifft_corr_kernel() {
    __shared__ float2 s[Lk];
    int b = blockIdx.x;
    for (int f = threadIdx.x; f < Lk; f += blockDim.x) {
        float2 v;
        if (f <= Lk/2) { float2 sf = g_S[b * NFk + f]; v = make_float2(sf.x, -sf.y); }
        else           { v = g_S[b * NFk + (Lk - f)]; }
        int r = __brev((unsigned)f) >> (32 - 12);
        s[r] = v;
    }
    __syncthreads();
    fft_core(s);
    float scale = 1.0f / ((float)Lk * (float)Dk);
    for (int t = threadIdx.x; t < Lk; t += blockDim.x)
        g_corr[b * Lk + t] = s[t].x * scale;
}

// top-8 + softmax
__global__ void topk_kernel() {
    int b = blockIdx.x;
    const float* c = g_corr + b * Lk;
    __shared__ float sv[256];
    __shared__ int   si[256];
    __shared__ int   ch_i[KTOP];
    __shared__ float ch_v[KTOP];
    int tid = threadIdx.x;
    for (int it = 0; it < KTOP; it++) {
        float bv = -3.402823e38f; int bi = 0x7fffffff;
        for (int t = tid; t < Lk; t += 256) {
            bool skip = false;
            for (int q = 0; q < it; q++) if (ch_i[q] == t) skip = true;
            if (skip) continue;
            float v = c[t];
            if (v > bv || (v == bv && t < bi)) { bv = v; bi = t; }
        }
        sv[tid] = bv; si[tid] = bi;
        __syncthreads();
        for (int st = 128; st > 0; st >>= 1) {
            if (tid < st) {
                if (sv[tid+st] > sv[tid] || (sv[tid+st] == sv[tid] && si[tid+st] < si[tid])) {
                    sv[tid] = sv[tid+st]; si[tid] = si[tid+st];
                }
            }
            __syncthreads();
        }
        if (tid == 0) { ch_i[it] = si[0]; ch_v[it] = sv[0]; }
        __syncthreads();
    }
    if (tid == 0) {
        float m = ch_v[0];
        for (int q = 1; q < KTOP; q++) m = fmaxf(m, ch_v[q]);
        float e[KTOP]; float sum = 0.f;
        for (int q = 0; q < KTOP; q++) { e[q] = expf(ch_v[q] - m); sum += e[q]; }
        for (int q = 0; q < KTOP; q++) {
            g_p[b*KTOP+q]     = e[q] / sum;
            g_delay[b*KTOP+q] = ch_i[q];
        }
    }
}

// attn (bf16 hi/lo) = sum_j p_j * V[b,(t+delay_j)%L,:]
__global__ void gather_kernel() {
    int bt = blockIdx.x;
    int b = bt >> 12, t = bt & (Lk - 1);
    __shared__ float pp[KTOP];
    __shared__ int   dd[KTOP];
    if (threadIdx.x < KTOP) {
        pp[threadIdx.x] = g_p[b*KTOP + threadIdx.x];
        dd[threadIdx.x] = g_delay[b*KTOP + threadIdx.x];
    }
    __syncthreads();
    int d = threadIdx.x * 4;
    float4 acc = make_float4(0.f, 0.f, 0.f, 0.f);
    #pragma unroll
    for (int j = 0; j < KTOP; j++) {
        int src = (t + dd[j]) & (Lk - 1);
        float4 v = *(const float4*)&g_V[(((size_t)b * Lk) + src) * Dk + d];
        acc.x += pp[j] * v.x; acc.y += pp[j] * v.y;
        acc.z += pp[j] * v.z; acc.w += pp[j] * v.w;
    }
    size_t o = (size_t)bt * Dk + d;
    uint32_t h0, l0, h1, l1;
    split2(acc.x, acc.y, h0, l0);
    split2(acc.z, acc.w, h1, l1);
    *(uint2*)&g_at_h[o] = make_uint2(h0, h1);
    *(uint2*)&g_at_l[o] = make_uint2(l0, l1);
}

// out = h - avgpool_same(h,25); optional bf16 hi/lo copy. chunk=64 rows/block.
__global__ void pool_kernel(const float* __restrict__ h, float* __restrict__ out,
                            __nv_bfloat16* __restrict__ oh, __nv_bfloat16* __restrict__ ol) {
    int b  = blockIdx.y;
    int t0 = blockIdx.x * 64;
    int d  = threadIdx.x;
    const float* hb = h   + (size_t)b * Lk * Dk + d;
    float*       ob = out + (size_t)b * Lk * Dk + d;
    float sum = 0.f;
    int lo = t0 - 12 < 0 ? 0 : t0 - 12;
    int hi = t0 + 12 > Lk - 1 ? Lk - 1 : t0 + 12;
    for (int t = lo; t <= hi; t++) sum += hb[(size_t)t * Dk];
    for (int t = t0; t < t0 + 64; t++) {
        int wlo = t - 12 < 0 ? 0 : t - 12;
        int whi = t + 12 > Lk - 1 ? Lk - 1 : t + 12;
        float cnt = (float)(whi - wlo + 1);
        float v = hb[(size_t)t * Dk] - sum / cnt;
        ob[(size_t)t * Dk] = v;
        if (oh) {
            size_t o = ((size_t)b * Lk + t) * Dk + d;
            __nv_bfloat16 hh = __float2bfloat16(v);
            oh[o] = hh;
            ol[o] = __float2bfloat16(v - __bfloat162float(hh));
        }
        int add = t + 13; if (add < Lk)  sum += hb[(size_t)add * Dk];
        int rem = t - 12; if (rem >= 0)  sum -= hb[(size_t)rem * Dk];
    }
}

// ---------------- launch ----------------
extern "C" void kernel_launch(void* const* d_in, const int* in_sizes, int n_in,
                              void* d_out, int out_size) {
    const float* x  = (const float*)d_in[0];
    const float* Wq = (const float*)d_in[1];
    const float* bq = (const float*)d_in[2];
    const float* Wk = (const float*)d_in[3];
    const float* bk = (const float*)d_in[4];
    const float* Wv = (const float*)d_in[5];
    const float* bv = (const float*)d_in[6];
    const float* Wo = (const float*)d_in[7];
    const float* bo = (const float*)d_in[8];
    const float* W1 = (const float*)d_in[9];
    const float* b1 = (const float*)d_in[10];
    const float* W2 = (const float*)d_in[11];
    const float* b2 = (const float*)d_in[12];
    float* out = (float*)d_out;

    float *pV, *pVU, *ph, *pS1, *ph2, *pG;
    __nv_bfloat16 *pxh,*pxl,*pUh,*pUl,*path,*patl,*pS1h,*pS1l,*phidh,*phidl;
    __nv_bfloat16 *pWvt_h,*pWvt_l,*pWot_h,*pWot_l,*pW1t_h,*pW1t_l,*pW2t_h,*pW2t_l;
    __nv_bfloat16 *pWq_h,*pWq_l,*pWk_h,*pWk_l,*pGt_h,*pGt_l;
    cudaGetSymbolAddress((void**)&pV,    g_V);
    cudaGetSymbolAddress((void**)&pVU,   g_VU);
    cudaGetSymbolAddress((void**)&ph,    g_h);
    cudaGetSymbolAddress((void**)&pS1,   g_S1);
    cudaGetSymbolAddress((void**)&ph2,   g_h2);
    cudaGetSymbolAddress((void**)&pG,    g_G);
    cudaGetSymbolAddress((void**)&pxh,   g_x_h);   cudaGetSymbolAddress((void**)&pxl,   g_x_l);
    cudaGetSymbolAddress((void**)&pUh,   g_U_h);   cudaGetSymbolAddress((void**)&pUl,   g_U_l);
    cudaGetSymbolAddress((void**)&path,  g_at_h);  cudaGetSymbolAddress((void**)&patl,  g_at_l);
    cudaGetSymbolAddress((void**)&pS1h,  g_S1_h);  cudaGetSymbolAddress((void**)&pS1l,  g_S1_l);
    cudaGetSymbolAddress((void**)&phidh, g_hid_h); cudaGetSymbolAddress((void**)&phidl, g_hid_l);
    cudaGetSymbolAddress((void**)&pWvt_h, g_Wvt_h); cudaGetSymbolAddress((void**)&pWvt_l, g_Wvt_l);
    cudaGetSymbolAddress((void**)&pWot_h, g_Wot_h); cudaGetSymbolAddress((void**)&pWot_l, g_Wot_l);
    cudaGetSymbolAddress((void**)&pW1t_h, g_W1t_h); cudaGetSymbolAddress((void**)&pW1t_l, g_W1t_l);
    cudaGetSymbolAddress((void**)&pW2t_h, g_W2t_h); cudaGetSymbolAddress((void**)&pW2t_l, g_W2t_l);
    cudaGetSymbolAddress((void**)&pWq_h,  g_Wq_h);  cudaGetSymbolAddress((void**)&pWq_l,  g_Wq_l);
    cudaGetSymbolAddress((void**)&pWk_h,  g_Wk_h);  cudaGetSymbolAddress((void**)&pWk_l,  g_Wk_l);
    cudaGetSymbolAddress((void**)&pGt_h,  g_Gt_h);  cudaGetSymbolAddress((void**)&pGt_l,  g_Gt_l);

    const int MR = Bk * Lk;              // 16384
    const int MUt = (RT + 127) / 128;    // 129
    dim3 wb(32, 8);

    init_tw_kernel<<<(Lk/2 + 255)/256, 256>>>();                                     // 1
    wprep_kernel<<<dim3(Dk/32,  Dk/32),  wb>>>(Wv, pWvt_h, pWvt_l, Dk, Dk);          // 2
    wsplit_kernel<<<(MR*Dk/2 + 255)/256, 256>>>(x, pxh, pxl, MR*Dk);                 // 3
    mmgemm_kernel<false><<<dim3(Dk/128, MR/128), 256>>>(                             // 4: V = x@Wv + bv
        pxh, pxl, pWvt_h, pWvt_l, bv, nullptr, pV, nullptr, nullptr, MR, Dk, Dk);
    fft_x_kernel<<<dim3(Bk, Dk/2), 512>>>(x);                                        // 5
    utsplit_kernel<<<dim3((RT + 31)/32, Dk/32), wb>>>();                             // 6
    wsplit_kernel<<<(Dk*Dk/2 + 255)/256, 256>>>(Wq, pWq_h, pWq_l, Dk*Dk);            // 7
    wsplit_kernel<<<(Dk*Dk/2 + 255)/256, 256>>>(Wk, pWk_h, pWk_l, Dk*Dk);            // 8
    mmgemm_kernel<false><<<dim3(Dk/128, Dk/128), 256>>>(                             // 9: G = Wq@Wk^T
        pWq_h, pWq_l, pWk_h, pWk_l, nullptr, nullptr, pG, nullptr, nullptr, Dk, Dk, Dk);
    wprep_kernel<<<dim3(Dk/32, Dk/32), wb>>>(pG, pGt_h, pGt_l, Dk, Dk);              // 10
    mmgemm_kernel<false><<<dim3(Dk/128, MUt), 256>>>(                                // 11: VU = U@G
        pUh, pUl, pGt_h, pGt_l, nullptr, nullptr, pVU, nullptr, nullptr, RT, Dk, Dk);
    sreduce_kernel<<<Bk * NFk, 128>>>();                                             // 12
    s0fix_kernel<<<Bk, Dk>>>(Wq, bq, Wk, bk);                                        // 13
    ifft_corr_kernel<<<Bk, 512>>>();                                                 // 14
    topk_kernel<<<Bk, 256>>>();                                                      // 15
    gather_kernel<<<Bk * Lk, 128>>>();                                               // 16
    wprep_kernel<<<dim3(Dk/32, Dk/32), wb>>>(Wo, pWot_h, pWot_l, Dk, Dk);            // 17
    mmgemm_kernel<false><<<dim3(Dk/128, MR/128), 256>>>(                             // 18: h = attn@Wo + bo + x
        path, patl, pWot_h, pWot_l, bo, x, ph, nullptr, nullptr, MR, Dk, Dk);
    pool_kernel<<<dim3(Lk/64, Bk), 512>>>(ph, pS1, pS1h, pS1l);                      // 19
    wprep_kernel<<<dim3(DFFk/32, Dk/32), wb>>>(W1, pW1t_h, pW1t_l, Dk, DFFk);        // 20
    mmgemm_kernel<true><<<dim3(DFFk/128, MR/128), 256>>>(                            // 21: hid = relu(S1@W1+b1)
        pS1h, pS1l, pW1t_h, pW1t_l, b1, nullptr, nullptr, phidh, phidl, MR, DFFk, Dk);
    wprep_kernel<<<dim3(Dk/32, DFFk/32), wb>>>(W2, pW2t_h, pW2t_l, DFFk, Dk);        // 22
    mmgemm_kernel<true><<<dim3(Dk/128, MR/128), 256>>>(                              // 23: h2 = relu(hid@W2+b2)+S1
        phidh, phidl, pW2t_h, pW2t_l, b2, pS1, ph2, nullptr, nullptr, MR, Dk, DFFk);
    pool_kernel<<<dim3(Lk/64, Bk), 512>>>(ph2, out, nullptr, nullptr);               // 24
}

// round 13
// speedup vs baseline: 1.1254x; 1.1224x over previous
#include <cuda_runtime.h>
#include <cuda_bf16.h>
#include <math.h>
#include <stdint.h>

#define Bk   4
#define Lk   4096
#define Dk   512
#define DFFk 2048
#define NFk  2049          // rfft bins = L/2+1
#define KTOP 8
#define PI_D 3.14159265358979323846
#define RT   (2*Bk*NFk)    // 16392 spectrum rows (re block ; im block)

// ---------------- scratch (static device globals; no allocation) ----------------
__device__ float  g_V    [Bk*Lk*Dk];
__device__ float  g_xr   [Bk*Lk*Dk];        // tf32-rounded x
__device__ float  g_Ut   [(size_t)Dk*RT];   // transposed spectrum [d][r]
__device__ float  g_U    [(size_t)RT*Dk];   // [r][d] (tf32-rounded)
__device__ float  g_VU   [(size_t)RT*Dk];
__device__ float2 g_S    [Bk*NFk];
__device__ float  g_corr [Bk*Lk];
__device__ int    g_delay[Bk*KTOP];
__device__ float  g_p    [Bk*KTOP];
__device__ float  g_attn [Bk*Lk*Dk];        // tf32-rounded
__device__ float  g_h    [Bk*Lk*Dk];
__device__ float  g_S1   [Bk*Lk*Dk];
__device__ float  g_S1r  [Bk*Lk*Dk];        // tf32-rounded
__device__ float  g_hid  [(size_t)Bk*Lk*DFFk];  // tf32-rounded
__device__ float  g_h2   [Bk*Lk*Dk];
__device__ float2 g_tw   [Lk/2];
__device__ float  g_G    [Dk*Dk];

// tf32-rounded weights ([N,K] layout for mma B operand = W^T)
__device__ float g_Wvt[Dk*Dk];
__device__ float g_Wot[Dk*Dk];
__device__ float g_W1t[DFFk*Dk];
__device__ float g_W2t[(size_t)Dk*DFFk];
__device__ float g_Wqr[Dk*Dk];
__device__ float g_Wkr[Dk*Dk];
__device__ float g_Gt [Dk*Dk];

// ---------------- helpers ----------------
__device__ __forceinline__ float totf32(float v) {
    uint32_t r;
    asm("cvt.rna.tf32.f32 %0, %1;" : "=r"(r) : "f"(v));
    return __uint_as_float(r);
}
__device__ __forceinline__ void cpa16(uint32_t dst, const void* src) {
    asm volatile("cp.async.cg.shared.global [%0], [%1], 16;" :: "r"(dst), "l"(src));
}
__device__ __forceinline__ void cpa_commit() { asm volatile("cp.async.commit_group;"); }
__device__ __forceinline__ void mma_tf32(float* c, const uint32_t* a,
                                         uint32_t b0, uint32_t b1) {
    asm volatile(
        "mma.sync.aligned.m16n8k8.row.col.f32.tf32.tf32.f32 "
        "{%0,%1,%2,%3}, {%4,%5,%6,%7}, {%8,%9}, {%0,%1,%2,%3};"
        : "+f"(c[0]), "+f"(c[1]), "+f"(c[2]), "+f"(c[3])
        : "r"(a[0]), "r"(a[1]), "r"(a[2]), "r"(a[3]), "r"(b0), "r"(b1));
}

// ---------------- double-buffered cp.async TF32 GEMM ----------------
// C = act(A @ B^T + bias) + res ; A [M,K], B [N,K], both fp32 pre-rounded to tf32.
// CTA 128x128, BK=16, 256 thr, 8 warps of 32x64. smem = 2 stages x 20KB = 40KB static.
#define ROWF 20                         // floats per padded row (16 data + 4 pad)
#define TILEF (128*ROWF)                // 2560
#define STAGEF (2*TILEF)                // 5120 (A tile + B tile)

template<bool RELU>
__global__ void __launch_bounds__(256, 2)
mmgemm_kernel(const float* __restrict__ A, const float* __restrict__ B,
              const float* __restrict__ bias, const float* __restrict__ res,
              float* __restrict__ C, float* __restrict__ Cr,
              int M, int N, int K)
{
    __shared__ float smem[2 * STAGEF];   // 40960 bytes
    const uint32_t* su = (const uint32_t*)smem;

    const int tid = threadIdx.x;
    const int bm  = blockIdx.y * 128;
    const int bn  = blockIdx.x * 128;
    const int w   = tid >> 5;
    const int l   = tid & 31;
    const int g   = l >> 2;
    const int t   = l & 3;
    const int wm  = (w & 3) * 32;
    const int wn  = (w >> 2) * 64;

    const uint32_t sbase = (uint32_t)__cvta_generic_to_shared(smem);

    float acc[2][8][4];
    #pragma unroll
    for (int i = 0; i < 2; i++)
        #pragma unroll
        for (int j = 0; j < 8; j++)
            #pragma unroll
            for (int e = 0; e < 4; e++) acc[i][j][e] = 0.f;

    const int irow = tid >> 1;
    const int ih   = tid & 1;
    const int am   = bm + irow < M ? bm + irow : M - 1;
    const size_t aoff = (size_t)am * K + ih * 8;
    const size_t boff = (size_t)(bn + irow) * K + ih * 8;

    const int NS = K >> 4;

    auto issue = [&](int s, int buf) {
        const int k0 = s << 4;
        uint32_t d = sbase + (uint32_t)(buf * STAGEF + irow * ROWF + ih * 8) * 4u;
        cpa16(d,                A + aoff + k0);
        cpa16(d + 16,           A + aoff + k0 + 4);
        cpa16(d + TILEF*4,      B + boff + k0);
        cpa16(d + TILEF*4 + 16, B + boff + k0 + 4);
        cpa_commit();
    };

    issue(0, 0);

    for (int s = 0; s < NS; s++) {
        const int buf = s & 1;
        if (s + 1 < NS) {
            issue(s + 1, buf ^ 1);
            asm volatile("cp.async.wait_group 1;");
        } else {
            asm volatile("cp.async.wait_group 0;");
        }
        __syncthreads();

        const uint32_t* sA = su + buf * STAGEF;
        const uint32_t* sB = sA + TILEF;

        #pragma unroll
        for (int kk = 0; kk < 2; kk++) {
            const int kb = kk * 8 + t;
            uint32_t a[2][4];
            #pragma unroll
            for (int i = 0; i < 2; i++) {
                int r0 = (wm + i * 16 + g) * ROWF;
                int r8 = r0 + 8 * ROWF;
                a[i][0] = sA[r0 + kb];     a[i][1] = sA[r8 + kb];
                a[i][2] = sA[r0 + kb + 4]; a[i][3] = sA[r8 + kb + 4];
            }
            #pragma unroll
            for (int j = 0; j < 8; j++) {
                int nr = (wn + j * 8 + g) * ROWF;
                uint32_t b0 = sB[nr + kb], b1 = sB[nr + kb + 4];
                #pragma unroll
                for (int i = 0; i < 2; i++)
                    mma_tf32(acc[i][j], a[i], b0, b1);
            }
        }
        __syncthreads();
    }

    // ---- epilogue ----
    #pragma unroll
    for (int i = 0; i < 2; i++) {
        #pragma unroll
        for (int half = 0; half < 2; half++) {
            int row = bm + wm + i * 16 + g + half * 8;
            if (row >= M) continue;
            size_t cr = (size_t)row * N;
            #pragma unroll
            for (int j = 0; j < 8; j++) {
                int col = bn + wn + j * 8 + 2 * t;
                float v0 = acc[i][j][half * 2 + 0];
                float v1 = acc[i][j][half * 2 + 1];
                if (bias) { v0 += __ldg(&bias[col]); v1 += __ldg(&bias[col + 1]); }
                if (RELU) { v0 = fmaxf(v0, 0.f); v1 = fmaxf(v1, 0.f); }
                if (res)  { v0 += res[cr + col]; v1 += res[cr + col + 1]; }
                if (C)    *(float2*)&C[cr + col] = make_float2(v0, v1);
                if (Cr)   *(float2*)&Cr[cr + col] = make_float2(totf32(v0), totf32(v1));
            }
        }
    }
}

// ---------------- weight prep: transpose fp32 [K,N] -> tf32-rounded [N,K] ----------------
__global__ void wprep_kernel(const float* __restrict__ W, float* __restrict__ Wt,
                             int K, int N) {
    __shared__ float t[32][33];
    int n0 = blockIdx.x * 32, k0 = blockIdx.y * 32;
    int tx = threadIdx.x, ty0 = threadIdx.y;
    #pragma unroll
    for (int j = 0; j < 32; j += 8) {
        int ty = ty0 + j;
        t[ty][tx] = W[(size_t)(k0 + ty) * N + n0 + tx];
    }
    __syncthreads();
    #pragma unroll
    for (int j = 0; j < 32; j += 8) {
        int ty = ty0 + j;
        Wt[(size_t)(n0 + ty) * K + k0 + tx] = totf32(t[tx][ty]);
    }
}

// elementwise tf32 round copy
__global__ void round_kernel(const float* __restrict__ W, float* __restrict__ R, int n) {
    int i = (blockIdx.x * blockDim.x + threadIdx.x) * 2;
    if (i < n) {
        float2 v = *(const float2*)(W + i);
        *(float2*)&R[i] = make_float2(totf32(v.x), totf32(v.y));
    }
}

// transpose Ut[d][r] -> U[r][d] (tf32-rounded)
__global__ void utsplit_kernel() {
    __shared__ float tb[32][33];
    int r0 = blockIdx.x * 32, d0 = blockIdx.y * 32;
    int tx = threadIdx.x, ty0 = threadIdx.y;
    #pragma unroll
    for (int j = 0; j < 32; j += 8) {
        int d = d0 + ty0 + j, r = r0 + tx;
        tb[ty0 + j][tx] = (r < RT) ? g_Ut[(size_t)d * RT + r] : 0.f;
    }
    __syncthreads();
    #pragma unroll
    for (int j = 0; j < 32; j += 8) {
        int r = r0 + ty0 + j, d = d0 + tx;
        if (r < RT) g_U[(size_t)r * Dk + d] = totf32(tb[tx][ty0 + j]);
    }
}

// ---------------- twiddle init ----------------
__global__ void init_tw_kernel() {
    int k = blockIdx.x * blockDim.x + threadIdx.x;
    if (k < Lk/2) {
        double ang = -2.0 * PI_D * (double)k / (double)Lk;
        g_tw[k] = make_float2((float)cos(ang), (float)sin(ang));
    }
}

// ---------------- FFT core ----------------
__device__ __forceinline__ void fft_core(float2* s) {
    for (int len = 2; len <= Lk; len <<= 1) {
        int half = len >> 1;
        int lh   = __ffs(half) - 1;
        int tws  = Lk / len;
        for (int j = threadIdx.x; j < Lk/2; j += blockDim.x) {
            int k  = j & (half - 1);
            int g  = j >> lh;
            int i0 = g * len + k;
            int i1 = i0 + half;
            float2 w = g_tw[k * tws];
            float2 a = s[i0], b = s[i1];
            float tre = w.x * b.x - w.y * b.y;
            float tim = w.x * b.y + w.y * b.x;
            s[i1] = make_float2(a.x - tre, a.y - tim);
            s[i0] = make_float2(a.x + tre, a.y + tim);
        }
        __syncthreads();
    }
}

// forward FFT of x, writes transposed spectrum Ut[d][r] (coalesced)
__global__ void fft_x_kernel(const float* __restrict__ x) {
    __shared__ float2 s[Lk];
    int b  = blockIdx.x;
    int pr = blockIdx.y;
    int d0 = 2 * pr, d1 = d0 + 1;
    const float* xb = x + (size_t)b * Lk * Dk;
    for (int t = threadIdx.x; t < Lk; t += blockDim.x) {
        int r = __brev((unsigned)t) >> (32 - 12);
        s[r] = make_float2(xb[(size_t)t * Dk + d0], xb[(size_t)t * Dk + d1]);
    }
    __syncthreads();
    fft_core(s);
    const int BNF = Bk * NFk;
    float* u0re = g_Ut + (size_t)d0 * RT + b * NFk;
    float* u0im = u0re + BNF;
    float* u1re = g_Ut + (size_t)d1 * RT + b * NFk;
    float* u1im = u1re + BNF;
    for (int f = threadIdx.x; f <= Lk/2; f += blockDim.x) {
        float2 zf = s[f];
        float2 zn = s[(Lk - f) & (Lk - 1)];
        u0re[f] = 0.5f * (zf.x + zn.x);
        u0im[f] = 0.5f * (zf.y - zn.y);
        u1re[f] = 0.5f * (zf.y + zn.y);
        u1im[f] = 0.5f * (zn.x - zf.x);
    }
}

// S[b,f] = VU[b,f,:] . conj(U[b,f,:])
__global__ void sreduce_kernel() {
    int row = blockIdx.x;
    const float* vre = g_VU + (size_t)row * Dk;
    const float* vim = g_VU + ((size_t)(Bk*NFk) + row) * Dk;
    const float* ure = g_U  + (size_t)row * Dk;
    const float* uim = g_U  + ((size_t)(Bk*NFk) + row) * Dk;
    float sre = 0.f, sim = 0.f;
    for (int d = threadIdx.x; d < Dk; d += blockDim.x) {
        float vr = vre[d], vi = vim[d], ur = ure[d], ui = uim[d];
        sre += vr * ur + vi * ui;
        sim += vi * ur - vr * ui;
    }
    __shared__ float rre[128], rim[128];
    int tid = threadIdx.x;
    rre[tid] = sre; rim[tid] = sim;
    __syncthreads();
    for (int st = 64; st > 0; st >>= 1) {
        if (tid < st) { rre[tid] += rre[tid + st]; rim[tid] += rim[tid + st]; }
        __syncthreads();
    }
    if (tid == 0) g_S[row] = make_float2(rre[0], rim[0]);
}

// exact fp32 S at f=0
__global__ void s0fix_kernel(const float* __restrict__ Wq, const float* __restrict__ bq,
                             const float* __restrict__ Wk, const float* __restrict__ bk) {
    int b = blockIdx.x;
    int i = threadIdx.x;
    __shared__ float u0[Dk];
    const float* ur = g_U + (size_t)(b * NFk) * Dk;
    u0[i] = ur[i];
    __syncthreads();
    float q = 0.f, k = 0.f;
    for (int t = 0; t < Dk; t++) {
        float u = u0[t];
        q += u * Wq[(size_t)t * Dk + i];
        k += u * Wk[(size_t)t * Dk + i];
    }
    q += (float)Lk * bq[i];
    k += (float)Lk * bk[i];
    __shared__ float red[Dk];
    red[i] = q * k;
    __syncthreads();
    for (int st = 256; st > 0; st >>= 1) {
        if (i < st) red[i] += red[i + st];
        __syncthreads();
    }
    if (i == 0) g_S[b * NFk] = make_float2(red[0], 0.f);
}

__global__ void ifft_corr_kernel() {
    __shared__ float2 s[Lk];
    int b = blockIdx.x;
    for (int f = threadIdx.x; f < Lk; f += blockDim.x) {
        float2 v;
        if (f <= Lk/2) { float2 sf = g_S[b * NFk + f]; v = make_float2(sf.x, -sf.y); }
        else           { v = g_S[b * NFk + (Lk - f)]; }
        int r = __brev((unsigned)f) >> (32 - 12);
        s[r] = v;
    }
    __syncthreads();
    fft_core(s);
    float scale = 1.0f / ((float)Lk * (float)Dk);
    for (int t = threadIdx.x; t < Lk; t += blockDim.x)
        g_corr[b * Lk + t] = s[t].x * scale;
}

// top-8 + softmax
__global__ void topk_kernel() {
    int b = blockIdx.x;
    const float* c = g_corr + b * Lk;
    __shared__ float sv[256];
    __shared__ int   si[256];
    __shared__ int   ch_i[KTOP];
    __shared__ float ch_v[KTOP];
    int tid = threadIdx.x;
    for (int it = 0; it < KTOP; it++) {
        float bv = -3.402823e38f; int bi = 0x7fffffff;
        for (int t = tid; t < Lk; t += 256) {
            bool skip = false;
            for (int q = 0; q < it; q++) if (ch_i[q] == t) skip = true;
            if (skip) continue;
            float v = c[t];
            if (v > bv || (v == bv && t < bi)) { bv = v; bi = t; }
        }
        sv[tid] = bv; si[tid] = bi;
        __syncthreads();
        for (int st = 128; st > 0; st >>= 1) {
            if (tid < st) {
                if (sv[tid+st] > sv[tid] || (sv[tid+st] == sv[tid] && si[tid+st] < si[tid])) {
                    sv[tid] = sv[tid+st]; si[tid] = si[tid+st];
                }
            }
            __syncthreads();
        }
        if (tid == 0) { ch_i[it] = si[0]; ch_v[it] = sv[0]; }
        __syncthreads();
    }
    if (tid == 0) {
        float m = ch_v[0];
        for (int q = 1; q < KTOP; q++) m = fmaxf(m, ch_v[q]);
        float e[KTOP]; float sum = 0.f;
        for (int q = 0; q < KTOP; q++) { e[q] = expf(ch_v[q] - m); sum += e[q]; }
        for (int q = 0; q < KTOP; q++) {
            g_p[b*KTOP+q]     = e[q] / sum;
            g_delay[b*KTOP+q] = ch_i[q];
        }
    }
}

// attn (tf32-rounded) = sum_j p_j * V[b,(t+delay_j)%L,:]
__global__ void gather_kernel() {
    int bt = blockIdx.x;
    int b = bt >> 12, t = bt & (Lk - 1);
    __shared__ float pp[KTOP];
    __shared__ int   dd[KTOP];
    if (threadIdx.x < KTOP) {
        pp[threadIdx.x] = g_p[b*KTOP + threadIdx.x];
        dd[threadIdx.x] = g_delay[b*KTOP + threadIdx.x];
    }
    __syncthreads();
    int d = threadIdx.x * 4;
    float4 acc = make_float4(0.f, 0.f, 0.f, 0.f);
    #pragma unroll
    for (int j = 0; j < KTOP; j++) {
        int src = (t + dd[j]) & (Lk - 1);
        float4 v = *(const float4*)&g_V[(((size_t)b * Lk) + src) * Dk + d];
        acc.x += pp[j] * v.x; acc.y += pp[j] * v.y;
        acc.z += pp[j] * v.z; acc.w += pp[j] * v.w;
    }
    float4 o = make_float4(totf32(acc.x), totf32(acc.y), totf32(acc.z), totf32(acc.w));
    *(float4*)&g_attn[(size_t)bt * Dk + d] = o;
}

// out = h - avgpool_same(h,25); optional tf32-rounded copy. chunk=64 rows/block.
__global__ void pool_kernel(const float* __restrict__ h, float* __restrict__ out,
                            float* __restrict__ orr) {
    int b  = blockIdx.y;
    int t0 = blockIdx.x * 64;
    int d  = threadIdx.x;
    const float* hb = h   + (size_t)b * Lk * Dk + d;
    float*       ob = out + (size_t)b * Lk * Dk + d;
    float sum = 0.f;
    int lo = t0 - 12 < 0 ? 0 : t0 - 12;
    int hi = t0 + 12 > Lk - 1 ? Lk - 1 : t0 + 12;
    for (int t = lo; t <= hi; t++) sum += hb[(size_t)t * Dk];
    for (int t = t0; t < t0 + 64; t++) {
        int wlo = t - 12 < 0 ? 0 : t - 12;
        int whi = t + 12 > Lk - 1 ? Lk - 1 : t + 12;
        float cnt = (float)(whi - wlo + 1);
        float v = hb[(size_t)t * Dk] - sum / cnt;
        ob[(size_t)t * Dk] = v;
        if (orr) orr[((size_t)b * Lk + t) * Dk + d] = totf32(v);
        int add = t + 13; if (add < Lk)  sum += hb[(size_t)add * Dk];
        int rem = t - 12; if (rem >= 0)  sum -= hb[(size_t)rem * Dk];
    }
}

// ---------------- launch ----------------
extern "C" void kernel_launch(void* const* d_in, const int* in_sizes, int n_in,
                              void* d_out, int out_size) {
    const float* x  = (const float*)d_in[0];
    const float* Wq = (const float*)d_in[1];
    const float* bq = (const float*)d_in[2];
    const float* Wk = (const float*)d_in[3];
    const float* bk = (const float*)d_in[4];
    const float* Wv = (const float*)d_in[5];
    const float* bv = (const float*)d_in[6];
    const float* Wo = (const float*)d_in[7];
    const float* bo = (const float*)d_in[8];
    const float* W1 = (const float*)d_in[9];
    const float* b1 = (const float*)d_in[10];
    const float* W2 = (const float*)d_in[11];
    const float* b2 = (const float*)d_in[12];
    float* out = (float*)d_out;

    float *pV, *pxr, *pVU, *ph, *pS1, *pS1r, *phid, *ph2, *pG, *pU, *pattn;
    float *pWvt, *pWot, *pW1t, *pW2t, *pWqr, *pWkr, *pGt;
    cudaGetSymbolAddress((void**)&pV,    g_V);
    cudaGetSymbolAddress((void**)&pxr,   g_xr);
    cudaGetSymbolAddress((void**)&pVU,   g_VU);
    cudaGetSymbolAddress((void**)&ph,    g_h);
    cudaGetSymbolAddress((void**)&pS1,   g_S1);
    cudaGetSymbolAddress((void**)&pS1r,  g_S1r);
    cudaGetSymbolAddress((void**)&phid,  g_hid);
    cudaGetSymbolAddress((void**)&ph2,   g_h2);
    cudaGetSymbolAddress((void**)&pG,    g_G);
    cudaGetSymbolAddress((void**)&pU,    g_U);
    cudaGetSymbolAddress((void**)&pattn, g_attn);
    cudaGetSymbolAddress((void**)&pWvt,  g_Wvt);
    cudaGetSymbolAddress((void**)&pWot,  g_Wot);
    cudaGetSymbolAddress((void**)&pW1t,  g_W1t);
    cudaGetSymbolAddress((void**)&pW2t,  g_W2t);
    cudaGetSymbolAddress((void**)&pWqr,  g_Wqr);
    cudaGetSymbolAddress((void**)&pWkr,  g_Wkr);
    cudaGetSymbolAddress((void**)&pGt,   g_Gt);

    const int MR = Bk * Lk;              // 16384
    const int MUt = (RT + 127) / 128;    // 129
    dim3 wb(32, 8);

    init_tw_kernel<<<(Lk/2 + 255)/256, 256>>>();                                     // 1
    wprep_kernel<<<dim3(Dk/32,  Dk/32),  wb>>>(Wv, pWvt, Dk, Dk);                    // 2
    round_kernel<<<(MR*Dk/2 + 255)/256, 256>>>(x, pxr, MR*Dk);                       // 3
    mmgemm_kernel<false><<<dim3(Dk/128, MR/128), 256>>>(                             // 4: V = x@Wv + bv
        pxr, pWvt, bv, nullptr, pV, nullptr, MR, Dk, Dk);
    fft_x_kernel<<<dim3(Bk, Dk/2), 512>>>(x);                                        // 5
    utsplit_kernel<<<dim3((RT + 31)/32, Dk/32), wb>>>();                             // 6
    round_kernel<<<(Dk*Dk/2 + 255)/256, 256>>>(Wq, pWqr, Dk*Dk);                     // 7
    round_kernel<<<(Dk*Dk/2 + 255)/256, 256>>>(Wk, pWkr, Dk*Dk);                     // 8
    mmgemm_kernel<false><<<dim3(Dk/128, Dk/128), 256>>>(                             // 9: G = Wq@Wk^T
        pWqr, pWkr, nullptr, nullptr, pG, nullptr, Dk, Dk, Dk);
    wprep_kernel<<<dim3(Dk/32, Dk/32), wb>>>(pG, pGt, Dk, Dk);                       // 10
    mmgemm_kernel<false><<<dim3(Dk/128, MUt), 256>>>(                                // 11: VU = U@G
        pU, pGt, nullptr, nullptr, pVU, nullptr, RT, Dk, Dk);
    sreduce_kernel<<<Bk * NFk, 128>>>();                                             // 12
    s0fix_kernel<<<Bk, Dk>>>(Wq, bq, Wk, bk);                                        // 13
    ifft_corr_kernel<<<Bk, 512>>>();                                                 // 14
    topk_kernel<<<Bk, 256>>>();                                                      // 15
    gather_kernel<<<Bk * Lk, 128>>>();                                               // 16
    wprep_kernel<<<dim3(Dk/32, Dk/32), wb>>>(Wo, pWot, Dk, Dk);                      // 17
    mmgemm_kernel<false><<<dim3(Dk/128, MR/128), 256>>>(                             // 18: h = attn@Wo + bo + x
        pattn, pWot, bo, x, ph, nullptr, MR, Dk, Dk);
    pool_kernel<<<dim3(Lk/64, Bk), 512>>>(ph, pS1, pS1r);                            // 19
    wprep_kernel<<<dim3(DFFk/32, Dk/32), wb>>>(W1, pW1t, Dk, DFFk);                  // 20
    mmgemm_kernel<true><<<dim3(DFFk/128, MR/128), 256>>>(                            // 21: hid = relu(S1@W1+b1)
        pS1r, pW1t, b1, nullptr, nullptr, phid, MR, DFFk, Dk);
    wprep_kernel<<<dim3(Dk/32, DFFk/32), wb>>>(W2, pW2t, DFFk, Dk);                  // 22
    mmgemm_kernel<true><<<dim3(Dk/128, MR/128), 256>>>(                              // 23: h2 = relu(hid@W2+b2)+S1
        phid, pW2t, b2, pS1, ph2, nullptr, MR, Dk, DFFk);
    pool_kernel<<<dim3(Lk/64, Bk), 512>>>(ph2, out, nullptr);                        // 24
}